// round 17
// baseline (speedup 1.0000x reference)
#include <cuda_runtime.h>
#include <cuda_fp16.h>
#include <cstdint>

#define IN_DIM  8192
#define OUT_DIM 8192
#define BATCH   8192
#define THREADS 1024
#define TEAM    512                       // threads per team (2 teams/CTA)
#define NGROUPS BATCH                     // R=1: one row per group, 8192 exact
#define GRID    148
#define KITERS  (OUT_DIM / TEAM)          // 16 j's per thread
#define GROUP_BYTES (IN_DIM * 4)          // 32768
// dynamic smem: 4 row buffers (2 per team): 4 * 32KB = 128 KB
#define SMEM_BYTES (4 * IN_DIM * 4)

// Meta in gmem: idx packed (regs once per thread); coeffs via __ldg (L1-resident).
__device__ unsigned g_mIdx[OUT_DIM];      // idx_a | idx_b<<13
__device__ uint2    g_coef[OUT_DIM];      // .x = half2(c0,c1), .y = half2(c2,c3)
__device__ unsigned g_ctr;                // work-stealing counter (shared by teams)

// GATE_COEFFS columns (16 rows x 4 cols, column-wise)
__constant__ float GATE0[16] = {0,0,0,0,0,0,0,0, 1, 1, 1, 1, 1, 1, 1, 1};
__constant__ float GATE1[16] = {0,0,1,1,0,0,1,1,-1,-1, 0, 0,-1,-1, 0, 0};
__constant__ float GATE2[16] = {0,0,0,0,1,1,1,1,-1,-1,-1,-1, 0, 0, 0, 0};
__constant__ float GATE3[16] = {0,1,-1,0,-1,0,-2,-1, 1, 2, 0, 1, 0, 1,-1, 0};

// ---------------------------------------------------------------------------
// Prep: softmax(weight[j]) @ GATE -> packed meta; reset steal counter.
// ---------------------------------------------------------------------------
__global__ void prep_kernel(const float* __restrict__ weight,
                            const int* __restrict__ idx_a,
                            const int* __restrict__ idx_b) {
    int j = blockIdx.x * blockDim.x + threadIdx.x;
    if (j == 0) g_ctr = 0;
    if (j >= OUT_DIM) return;

    const float4* wrow = reinterpret_cast<const float4*>(weight + (size_t)j * 16);
    float v[16];
    #pragma unroll
    for (int q = 0; q < 4; q++) {
        float4 w = wrow[q];
        v[q*4+0] = w.x; v[q*4+1] = w.y; v[q*4+2] = w.z; v[q*4+3] = w.w;
    }
    float m = v[0];
    #pragma unroll
    for (int k = 1; k < 16; k++) m = fmaxf(m, v[k]);
    float s = 0.0f;
    #pragma unroll
    for (int k = 0; k < 16; k++) { v[k] = expf(v[k] - m); s += v[k]; }
    float inv = 1.0f / s;

    float c0 = 0.f, c1 = 0.f, c2 = 0.f, c3 = 0.f;
    #pragma unroll
    for (int k = 0; k < 16; k++) {
        float wk = v[k] * inv;
        c0 = fmaf(wk, GATE0[k], c0);
        c1 = fmaf(wk, GATE1[k], c1);
        c2 = fmaf(wk, GATE2[k], c2);
        c3 = fmaf(wk, GATE3[k], c3);
    }

    g_mIdx[j] = (unsigned)idx_a[j] | ((unsigned)idx_b[j] << 13);
    __half2 c01 = __floats2half2_rn(c0, c1);
    __half2 c23 = __floats2half2_rn(c2, c3);
    uint2 rec;
    rec.x = *reinterpret_cast<unsigned*>(&c01);
    rec.y = *reinterpret_cast<unsigned*>(&c23);
    g_coef[j] = rec;
}

// ---------------------------------------------------------------------------
// TMA bulk 1D: one 32KB row GMEM -> SMEM, mbarrier tx completion.
// ---------------------------------------------------------------------------
__device__ __forceinline__ void tma_issue(float* smem_dst, const float* gmem_src,
                                          uint64_t* mbar) {
    uint32_t s  = (uint32_t)__cvta_generic_to_shared(smem_dst);
    uint32_t mb = (uint32_t)__cvta_generic_to_shared(mbar);
    asm volatile("mbarrier.arrive.expect_tx.shared.b64 _, [%0], %1;"
                 :: "r"(mb), "r"((unsigned)GROUP_BYTES) : "memory");
    asm volatile("cp.async.bulk.shared::cta.global.mbarrier::complete_tx::bytes "
                 "[%0], [%1], %2, [%3];"
                 :: "r"(s), "l"(gmem_src), "r"((unsigned)GROUP_BYTES), "r"(mb)
                 : "memory");
}

__device__ __forceinline__ void mbar_wait(uint64_t* mbar, unsigned parity) {
    uint32_t mb = (uint32_t)__cvta_generic_to_shared(mbar);
    asm volatile(
        "{\n\t"
        ".reg .pred P1;\n\t"
        "WAIT_LOOP_%=:\n\t"
        "mbarrier.try_wait.parity.acquire.cta.shared::cta.b64 P1, [%0], %1, 0x989680;\n\t"
        "@P1 bra.uni WAIT_DONE_%=;\n\t"
        "bra.uni WAIT_LOOP_%=;\n\t"
        "WAIT_DONE_%=:\n\t"
        "}"
        :: "r"(mb), "r"(parity) : "memory");
}

__device__ __forceinline__ void team_bar(int team) {
    asm volatile("bar.sync %0, %1;" :: "r"(team + 1), "r"(TEAM) : "memory");
}

// ---------------------------------------------------------------------------
// Main: persistent; TWO independent 512-thread teams per CTA, each with its own
// double-buffered TMA ring + named barrier + work stealing. Team A's sync/wait
// bubbles are covered by team B's gathers/stores.
// ---------------------------------------------------------------------------
extern "C" __global__ void __launch_bounds__(THREADS, 1)
logic_kernel(const float* __restrict__ x, float* __restrict__ out) {
    extern __shared__ float sm[];              // [4][IN_DIM]: team*2 + {0,1}
    __shared__ __align__(8) uint64_t mbar[4];
    __shared__ int s_q[2][2];
    const int tid  = threadIdx.x;
    const int team = tid >> 9;                 // 0 or 1
    const int ltid = tid & (TEAM - 1);

    // ---- idx slice into registers (once) ----
    unsigned mIdx[KITERS];
    #pragma unroll
    for (int k = 0; k < KITERS; k++) mIdx[k] = g_mIdx[ltid + k * TEAM];

    // ---- init barriers (block-wide once) ----
    if (tid == 0) {
        #pragma unroll
        for (int b = 0; b < 4; b++)
            asm volatile("mbarrier.init.shared.b64 [%0], 1;"
                         :: "r"((uint32_t)__cvta_generic_to_shared(&mbar[b])) : "memory");
    }
    __syncthreads();

    // ---- per-team first two steals + TMA kicks ----
    if (ltid == 0) {
        s_q[team][0] = (int)atomicAdd(&g_ctr, 1u);
        s_q[team][1] = (int)atomicAdd(&g_ctr, 1u);
    }
    team_bar(team);
    int g     = s_q[team][0];
    int gnext = s_q[team][1];
    if (ltid == 0) {
        if (g     < NGROUPS) tma_issue(sm + (team * 2 + 0) * IN_DIM,
                                       x + (size_t)g     * IN_DIM, &mbar[team * 2 + 0]);
        if (gnext < NGROUPS) tma_issue(sm + (team * 2 + 1) * IN_DIM,
                                       x + (size_t)gnext * IN_DIM, &mbar[team * 2 + 1]);
    }

    int cur = 0;
    unsigned ph0 = 0, ph1 = 0;

    while (g < NGROUPS) {
        if (ltid == 0) s_q[team][cur] = (int)atomicAdd(&g_ctr, 1u);

        mbar_wait(&mbar[team * 2 + cur], cur ? ph1 : ph0);

        // ---- compute this row (16 independent j-iters) ----
        const float* buf = sm + (team * 2 + cur) * IN_DIM;
        float* o = out + (size_t)g * OUT_DIM;
        #pragma unroll
        for (int k = 0; k < KITERS; k++) {
            int j = ltid + k * TEAM;
            unsigned pk = mIdx[k];
            unsigned ai = pk & 8191u;
            unsigned bi = pk >> 13;
            uint2 cc = __ldg(&g_coef[j]);      // LDG.64, L1-resident
            float2 c01 = __half22float2(*reinterpret_cast<const __half2*>(&cc.x));
            float2 c23 = __half22float2(*reinterpret_cast<const __half2*>(&cc.y));
            float a = buf[ai];
            float b = buf[bi];
            __stcg(o + j, fmaf(c23.y, a * b, fmaf(c23.x, b, fmaf(c01.y, a, c01.x))));
        }
        if (cur == 0) ph0 ^= 1; else ph1 ^= 1;

        team_bar(team);                        // gathers done; s_q visible
        int gnew = s_q[team][cur];
        if (ltid == 0 && gnew < NGROUPS)
            tma_issue(sm + (team * 2 + cur) * IN_DIM,
                      x + (size_t)gnew * IN_DIM, &mbar[team * 2 + cur]);

        g = gnext;
        gnext = gnew;
        cur ^= 1;
    }
}

// ---------------------------------------------------------------------------
// Launch: x (f32), weight (f32), idx_a (i32), idx_b (i32) -> out (f32)
// ---------------------------------------------------------------------------
extern "C" void kernel_launch(void* const* d_in, const int* in_sizes, int n_in,
                              void* d_out, int out_size) {
    const float* x      = (const float*)d_in[0];
    const float* weight = (const float*)d_in[1];
    const int*   idx_a  = (const int*)d_in[2];
    const int*   idx_b  = (const int*)d_in[3];
    float*       out    = (float*)d_out;

    cudaFuncSetAttribute(logic_kernel,
                         cudaFuncAttributeMaxDynamicSharedMemorySize, SMEM_BYTES);

    prep_kernel<<<OUT_DIM / 256, 256>>>(weight, idx_a, idx_b);
    logic_kernel<<<GRID, THREADS, SMEM_BYTES>>>(x, out);
}